// round 3
// baseline (speedup 1.0000x reference)
#include <cuda_runtime.h>
#include <cstdint>

#define B_   256
#define N_   144
#define D_   512
#define H_   8
#define M_   (B_ * N_)            // 36864 rows
#define SCALE_ 0.125f             // 64^-0.5

// ---------------- scratch (device globals: allocation-free rule) -------------
__device__ float g_kv [(size_t)M_ * 1024];   // [m, {k:0..511 | v:512..1023}], col = h*64+e
__device__ float g_q  [(size_t)M_ * 512];    // [m, h*64+e]
__device__ float g_att[(size_t)M_ * 512];    // [m, h*64+e]

// ---------------- packed f32x2 helpers (Blackwell FFMA2 path) ----------------
__device__ __forceinline__ unsigned long long pack2(float lo, float hi) {
    unsigned long long r;
    asm("mov.b64 %0, {%1, %2};" : "=l"(r) : "f"(lo), "f"(hi));
    return r;
}
__device__ __forceinline__ void fma2(unsigned long long& d, unsigned long long a, unsigned long long b) {
    asm("fma.rn.f32x2 %0, %1, %2, %0;" : "+l"(d) : "l"(a), "l"(b));
}
__device__ __forceinline__ float2 unpack2(unsigned long long v) {
    float2 r;
    asm("mov.b64 {%0, %1}, %2;" : "=f"(r.x), "=f"(r.y) : "l"(v));
    return r;
}

// ---------------- SGEMM:  C[M x Nc] = (A (+ f*A2)) @ W^T (+ bias) -------------
// (unchanged from round 1 — measured 92 TF/s, near fp32 roofline)
__global__ __launch_bounds__(256)
void gemm_nt_kernel(const float* __restrict__ A, const float* __restrict__ A2,
                    const int* __restrict__ flag,
                    const float* __restrict__ W, const float* __restrict__ bias,
                    float* __restrict__ C, int Nc)
{
    __shared__ float As[16][132];
    __shared__ float Ws[16][132];

    const int t    = threadIdx.x;
    const int row0 = blockIdx.y * 128;
    const int col0 = blockIdx.x * 128;
    const int lr   = t >> 2;
    const int lc   = (t & 3) << 2;
    const int tx   = t & 15;
    const int ty   = t >> 4;

    float addf = 0.f;
    if (A2) addf = (*flag != 0) ? 1.f : 0.f;

    unsigned long long acc[8][4];
#pragma unroll
    for (int i = 0; i < 8; i++)
#pragma unroll
        for (int j = 0; j < 4; j++) acc[i][j] = 0ull;

    const float* Abase  = A + (size_t)(row0 + lr) * 512 + lc;
    const float* A2base = A2 ? (A2 + (size_t)(row0 + lr) * 512 + lc) : nullptr;
    const float* Wbase  = W + (size_t)(col0 + lr) * 512 + lc;

    for (int k0 = 0; k0 < 512; k0 += 16) {
        float4 a0 = *(const float4*)(Abase + k0);
        float4 a1 = *(const float4*)(Abase + (size_t)64 * 512 + k0);
        if (A2) {
            float4 t0 = *(const float4*)(A2base + k0);
            float4 t1 = *(const float4*)(A2base + (size_t)64 * 512 + k0);
            a0.x += addf * t0.x; a0.y += addf * t0.y; a0.z += addf * t0.z; a0.w += addf * t0.w;
            a1.x += addf * t1.x; a1.y += addf * t1.y; a1.z += addf * t1.z; a1.w += addf * t1.w;
        }
        float4 w0 = *(const float4*)(Wbase + k0);
        float4 w1 = *(const float4*)(Wbase + (size_t)64 * 512 + k0);

        __syncthreads();
        As[lc + 0][lr]      = a0.x; As[lc + 1][lr]      = a0.y;
        As[lc + 2][lr]      = a0.z; As[lc + 3][lr]      = a0.w;
        As[lc + 0][lr + 64] = a1.x; As[lc + 1][lr + 64] = a1.y;
        As[lc + 2][lr + 64] = a1.z; As[lc + 3][lr + 64] = a1.w;
        Ws[lc + 0][lr]      = w0.x; Ws[lc + 1][lr]      = w0.y;
        Ws[lc + 2][lr]      = w0.z; Ws[lc + 3][lr]      = w0.w;
        Ws[lc + 0][lr + 64] = w1.x; Ws[lc + 1][lr + 64] = w1.y;
        Ws[lc + 2][lr + 64] = w1.z; Ws[lc + 3][lr + 64] = w1.w;
        __syncthreads();

#pragma unroll
        for (int kk = 0; kk < 16; kk++) {
            float4 av0 = *(const float4*)&As[kk][ty * 8];
            float4 av1 = *(const float4*)&As[kk][ty * 8 + 4];
            float4 bv0 = *(const float4*)&Ws[kk][tx * 8];
            float4 bv1 = *(const float4*)&Ws[kk][tx * 8 + 4];
            unsigned long long bp[4] = { pack2(bv0.x, bv0.y), pack2(bv0.z, bv0.w),
                                         pack2(bv1.x, bv1.y), pack2(bv1.z, bv1.w) };
            float ar[8] = { av0.x, av0.y, av0.z, av0.w, av1.x, av1.y, av1.z, av1.w };
#pragma unroll
            for (int i = 0; i < 8; i++) {
                unsigned long long ad = pack2(ar[i], ar[i]);
#pragma unroll
                for (int j = 0; j < 4; j++) fma2(acc[i][j], ad, bp[j]);
            }
        }
    }

#pragma unroll
    for (int i = 0; i < 8; i++) {
        size_t row = (size_t)(row0 + ty * 8 + i);
        float* Cp = C + row * (size_t)Nc + col0 + tx * 8;
        float2 r0 = unpack2(acc[i][0]);
        float2 r1 = unpack2(acc[i][1]);
        float2 r2 = unpack2(acc[i][2]);
        float2 r3 = unpack2(acc[i][3]);
        if (bias) {
            const float* bp = bias + col0 + tx * 8;
            r0.x += bp[0]; r0.y += bp[1]; r1.x += bp[2]; r1.y += bp[3];
            r2.x += bp[4]; r2.y += bp[5]; r3.x += bp[6]; r3.y += bp[7];
        }
        *(float4*)(Cp)     = make_float4(r0.x, r0.y, r1.x, r1.y);
        *(float4*)(Cp + 4) = make_float4(r2.x, r2.y, r3.x, r3.y);
    }
}

// ---------------- attention v2: outer-product GEMM structure ------------------
// One CTA per (b,h). 256 threads as 16x16 grid.
//   QK: S[144][144], micro-tile 9x9 per thread, K-loop over 64 (FMA-bound).
//   softmax: smem partial reductions (aliased into P panel), inv deferred to out.
//   PV: O[144][64], micro-tile 9x4 per thread, j-loop over 144.
// smem panels (pitch 145 -> 17 mod 32, gcd=1 -> conflict-free column writes):
#define AP   145
#define VP   68
#define QT_OFF 0
#define KT_OFF (64 * AP)
#define V_OFF  (2 * 64 * AP)
#define PT_OFF (2 * 64 * AP + 144 * VP)
#define ATTN_SMEM_FLOATS (2 * 64 * AP + 144 * VP + 144 * AP)
#define ATTN_SMEM_BYTES  (ATTN_SMEM_FLOATS * 4)

__global__ __launch_bounds__(256, 1)
void attn_kernel(const float* __restrict__ q, const float* __restrict__ kv,
                 float* __restrict__ o)
{
    extern __shared__ float sm[];
    float* Qt = sm + QT_OFF;     // [64][145]  Qt[k][r] = Q[r][k] * SCALE
    float* Kt = sm + KT_OFF;     // [64][145]  Kt[k][c] = K[c][k]
    float* Vs = sm + V_OFF;      // [144][68]
    float* Pt = sm + PT_OFF;     // [144][145] Pt[c][r] = exp(S[r][c]-m_r); aliases red[144][17]
    float* red = Pt;

    const int b = blockIdx.x >> 3;
    const int h = blockIdx.x & 7;
    const int t = threadIdx.x;
    const int ty = t >> 4;       // 0..15 (row group, 9 rows each)
    const int tx = t & 15;       // 0..15 (col group)

    const float* qb = q  + (size_t)b * 144 * 512  + h * 64;
    const float* kb = kv + (size_t)b * 144 * 1024 + h * 64;
    const float* vb = kb + 512;

    // ---- stage Q^T (scaled), K^T, V ----
    for (int i = t; i < 144 * 64; i += 256) {
        int r = i >> 6, k = i & 63;
        Qt[k * AP + r] = qb[(size_t)r * 512 + k] * SCALE_;
        Kt[k * AP + r] = kb[(size_t)r * 1024 + k];
    }
    for (int i = t; i < 144 * 16; i += 256) {
        int n = i >> 4, c = (i & 15) << 2;
        *(float4*)(Vs + n * VP + c) = *(const float4*)(vb + (size_t)n * 1024 + c);
    }
    __syncthreads();

    // ---- QK: acc[i][j] = sum_k Q[ty*9+i][k] * K[tx*9+j][k] ----
    float acc[9][9];
#pragma unroll
    for (int i = 0; i < 9; i++)
#pragma unroll
        for (int j = 0; j < 9; j++) acc[i][j] = 0.f;

    const float* Qb = Qt + ty * 9;
    const float* Kb = Kt + tx * 9;
#pragma unroll 2
    for (int k = 0; k < 64; k++) {
        float qv[9], kvv[9];
#pragma unroll
        for (int i = 0; i < 9; i++) qv[i]  = Qb[k * AP + i];
#pragma unroll
        for (int j = 0; j < 9; j++) kvv[j] = Kb[k * AP + j];
#pragma unroll
        for (int i = 0; i < 9; i++)
#pragma unroll
            for (int j = 0; j < 9; j++) acc[i][j] += qv[i] * kvv[j];
    }

    // ---- softmax (row-wise over 16 tx groups; red[r][17-pitch] aliases Pt) ----
#pragma unroll
    for (int i = 0; i < 9; i++) {
        float m = acc[i][0];
#pragma unroll
        for (int j = 1; j < 9; j++) m = fmaxf(m, acc[i][j]);
        red[(ty * 9 + i) * 17 + tx] = m;
    }
    __syncthreads();
    float mrow[9];
#pragma unroll
    for (int i = 0; i < 9; i++) {
        const float* rr = red + (ty * 9 + i) * 17;
        float m = rr[0];
#pragma unroll
        for (int u = 1; u < 16; u++) m = fmaxf(m, rr[u]);
        mrow[i] = m;
    }
    __syncthreads();
#pragma unroll
    for (int i = 0; i < 9; i++) {
        float s = 0.f;
#pragma unroll
        for (int j = 0; j < 9; j++) {
            float e = __expf(acc[i][j] - mrow[i]);
            acc[i][j] = e;
            s += e;
        }
        red[(ty * 9 + i) * 17 + tx] = s;
    }
    __syncthreads();
    float inv[9];
#pragma unroll
    for (int i = 0; i < 9; i++) {
        const float* rr = red + (ty * 9 + i) * 17;
        float s = rr[0];
#pragma unroll
        for (int u = 1; u < 16; u++) s += rr[u];
        inv[i] = 1.f / s;
    }
    __syncthreads();   // all reduction reads done before Pt overwrites red region

    // ---- store P transposed: Pt[c][r] ----
#pragma unroll
    for (int j = 0; j < 9; j++)
#pragma unroll
        for (int i = 0; i < 9; i++)
            Pt[(tx * 9 + j) * AP + (ty * 9 + i)] = acc[i][j];
    __syncthreads();

    // ---- PV: out[i][d4] = sum_j P[ty*9+i][j] * V[j][tx*4+d4] ----
    float out[9][4];
#pragma unroll
    for (int i = 0; i < 9; i++)
#pragma unroll
        for (int d = 0; d < 4; d++) out[i][d] = 0.f;

    const float* Pb = Pt + ty * 9;
#pragma unroll 2
    for (int j = 0; j < 144; j++) {
        float pv[9];
#pragma unroll
        for (int i = 0; i < 9; i++) pv[i] = Pb[j * AP + i];
        float4 vv = *(const float4*)(Vs + j * VP + tx * 4);
#pragma unroll
        for (int i = 0; i < 9; i++) {
            out[i][0] += pv[i] * vv.x;
            out[i][1] += pv[i] * vv.y;
            out[i][2] += pv[i] * vv.z;
            out[i][3] += pv[i] * vv.w;
        }
    }

    float* ob = o + (size_t)b * 144 * 512 + h * 64;
#pragma unroll
    for (int i = 0; i < 9; i++) {
        int r = ty * 9 + i;
        *(float4*)(ob + (size_t)r * 512 + tx * 4) =
            make_float4(out[i][0] * inv[i], out[i][1] * inv[i],
                        out[i][2] * inv[i], out[i][3] * inv[i]);
    }
}

// ---------------- launch -------------------------------------------------------
extern "C" void kernel_launch(void* const* d_in, const int* in_sizes, int n_in,
                              void* d_out, int out_size)
{
    const float* x      = (const float*)d_in[0];
    const float* topo   = (const float*)d_in[1];
    const float* kv_w   = (const float*)d_in[2];
    const float* q_w    = (const float*)d_in[3];
    const float* proj_w = (const float*)d_in[4];
    const float* proj_b = (const float*)d_in[5];
    const int*   is_end = (const int*)d_in[6];

    void *pkv = nullptr, *pq = nullptr, *patt = nullptr;
    cudaGetSymbolAddress(&pkv, g_kv);
    cudaGetSymbolAddress(&pq,  g_q);
    cudaGetSymbolAddress(&patt, g_att);
    float* fkv  = (float*)pkv;
    float* fq   = (float*)pq;
    float* fatt = (float*)patt;

    cudaFuncSetAttribute(attn_kernel, cudaFuncAttributeMaxDynamicSharedMemorySize,
                         ATTN_SMEM_BYTES);

    // KV = (x + is_end*topo) @ kv_w^T   [36864 x 1024]
    gemm_nt_kernel<<<dim3(8, 288), 256>>>(x, topo, is_end, kv_w, nullptr, fkv, 1024);
    // Q  = x @ q_w^T                    [36864 x 512]
    gemm_nt_kernel<<<dim3(4, 288), 256>>>(x, nullptr, nullptr, q_w, nullptr, fq, 512);
    // per-(b,h) softmax attention       -> g_att [36864 x 512] in [b,n,h,e] order
    attn_kernel<<<B_ * H_, 256, ATTN_SMEM_BYTES>>>(fq, fkv, fatt);
    // out = g_att @ proj_w^T + proj_b   -> d_out
    gemm_nt_kernel<<<dim3(4, 288), 256>>>(fatt, nullptr, nullptr, proj_w, proj_b,
                                          (float*)d_out, 512);
}

// round 4
// speedup vs baseline: 1.7689x; 1.7689x over previous
#include <cuda_runtime.h>
#include <cuda_bf16.h>
#include <cstdint>

#define B_   256
#define N_   144
#define M_   (B_ * N_)            // 36864 rows
#define SCALE_ 0.125f             // 64^-0.5

// ---------------- scratch (device globals: allocation-free rule) -------------
__device__ float g_kv [(size_t)M_ * 1024];
__device__ float g_q  [(size_t)M_ * 512];
__device__ float g_att[(size_t)M_ * 512];

// bf16 hi|lo split operands: [rows, 1024] = [hi(512) | lo(512)]
__device__ __nv_bfloat16 g_xte [(size_t)M_ * 1024];   // x + is_end*topo
__device__ __nv_bfloat16 g_xe  [(size_t)M_ * 1024];   // x
__device__ __nv_bfloat16 g_ae  [(size_t)M_ * 1024];   // attention out
__device__ __nv_bfloat16 g_wkve[(size_t)1024 * 1024];
__device__ __nv_bfloat16 g_wqe [(size_t)512 * 1024];
__device__ __nv_bfloat16 g_wpe [(size_t)512 * 1024];

// ---------------- helpers ------------------------------------------------------
__device__ __forceinline__ uint32_t smem_u32(const void* p) {
    uint32_t a;
    asm("{ .reg .u64 t; cvta.to.shared.u64 t, %1; cvt.u32.u64 %0, t; }" : "=r"(a) : "l"(p));
    return a;
}
__device__ __forceinline__ void ldsm_x4(uint32_t& r0, uint32_t& r1, uint32_t& r2,
                                        uint32_t& r3, uint32_t addr) {
    asm volatile("ldmatrix.sync.aligned.m8n8.x4.shared.b16 {%0,%1,%2,%3}, [%4];"
                 : "=r"(r0), "=r"(r1), "=r"(r2), "=r"(r3) : "r"(addr));
}
__device__ __forceinline__ void mma_bf16(float* c, uint32_t a0, uint32_t a1,
                                         uint32_t a2, uint32_t a3,
                                         uint32_t b0, uint32_t b1) {
    asm volatile(
        "mma.sync.aligned.m16n8k16.row.col.f32.bf16.bf16.f32 "
        "{%0,%1,%2,%3}, {%4,%5,%6,%7}, {%8,%9}, {%0,%1,%2,%3};"
        : "+f"(c[0]), "+f"(c[1]), "+f"(c[2]), "+f"(c[3])
        : "r"(a0), "r"(a1), "r"(a2), "r"(a3), "r"(b0), "r"(b1));
}
__device__ __forceinline__ void split1(float v, __nv_bfloat16& h, __nv_bfloat16& l) {
    h = __float2bfloat16_rn(v);
    l = __float2bfloat16_rn(v - __bfloat162float(h));
}

// ---------------- fp32 -> bf16 hi/lo split (single stream) --------------------
__global__ __launch_bounds__(256)
void split_bf16_kernel(const float4* __restrict__ in, __nv_bfloat16* __restrict__ out,
                       long total4)
{
    long i = (long)blockIdx.x * blockDim.x + threadIdx.x;
    if (i >= total4) return;
    float4 a = in[i];
    long idx = i * 4;
    long row = idx >> 9;
    int  col = (int)(idx & 511);
    float v[4] = { a.x, a.y, a.z, a.w };
    __nv_bfloat16 h[4], l[4];
#pragma unroll
    for (int j = 0; j < 4; j++) split1(v[j], h[j], l[j]);
    __nv_bfloat16* base = out + row * 1024 + col;
    *(uint2*)(base)       = *(uint2*)h;
    *(uint2*)(base + 512) = *(uint2*)l;
}

// dual: oxe = split(x), oxte = split(x + f*topo)  (reads x/topo once)
__global__ __launch_bounds__(256)
void split_dual_kernel(const float4* __restrict__ x, const float4* __restrict__ topo,
                       const int* __restrict__ flag,
                       __nv_bfloat16* __restrict__ oxe, __nv_bfloat16* __restrict__ oxte,
                       long total4)
{
    long i = (long)blockIdx.x * blockDim.x + threadIdx.x;
    if (i >= total4) return;
    float4 a = x[i];
    float4 tp = topo[i];
    float f = (*flag != 0) ? 1.f : 0.f;
    long idx = i * 4;
    long row = idx >> 9;
    int  col = (int)(idx & 511);
    float v1[4] = { a.x, a.y, a.z, a.w };
    float v2[4] = { a.x + f * tp.x, a.y + f * tp.y, a.z + f * tp.z, a.w + f * tp.w };
    __nv_bfloat16 h[4], l[4];
#pragma unroll
    for (int j = 0; j < 4; j++) split1(v1[j], h[j], l[j]);
    __nv_bfloat16* b1 = oxe + row * 1024 + col;
    *(uint2*)(b1)       = *(uint2*)h;
    *(uint2*)(b1 + 512) = *(uint2*)l;
#pragma unroll
    for (int j = 0; j < 4; j++) split1(v2[j], h[j], l[j]);
    __nv_bfloat16* b2 = oxte + row * 1024 + col;
    *(uint2*)(b2)       = *(uint2*)h;
    *(uint2*)(b2 + 512) = *(uint2*)l;
}

// ---------------- mma.sync bf16 GEMM: C = A_split @ W_split^T (+bias) ----------
// A: [M,1024] bf16 hi|lo, Bw: [Nc,1024] bf16 hi|lo. 3 passes: hi*hi, lo*hi, hi*lo.
// CTA tile 128x128, 8 warps (2x4) of 64x32 warp tiles. K chunks of 64 (24 total).
// smem pitch 72 bf16 = 144B (conflict-free ldmatrix phases).
#define GP 72

__global__ __launch_bounds__(256)
void gemm_mma_kernel(const __nv_bfloat16* __restrict__ A,
                     const __nv_bfloat16* __restrict__ Bw,
                     const float* __restrict__ bias,
                     float* __restrict__ C, int Nc)
{
    __shared__ __nv_bfloat16 sA[128 * GP];
    __shared__ __nv_bfloat16 sB[128 * GP];

    const int t    = threadIdx.x;
    const int lane = t & 31;
    const int w    = t >> 5;
    const int wm   = w >> 2;          // 0..1 : 64-row half
    const int wn   = w & 3;           // 0..3 : 32-col quarter
    const int row0 = blockIdx.y * 128;
    const int col0 = blockIdx.x * 128;

    const uint32_t sAu = smem_u32(sA);
    const uint32_t sBu = smem_u32(sB);

    // ldmatrix per-lane addresses (byte offsets, pitch 144B)
    const uint32_t aLane = sAu + (uint32_t)(wm * 64 + (lane & 15)) * 144 + (lane >> 4) * 16;
    const uint32_t bLane = sBu + (uint32_t)(wn * 32 + (lane & 7) + ((lane >> 4) & 1) * 8) * 144
                               + ((lane >> 3) & 1) * 16;

    float acc[4][4][4];
#pragma unroll
    for (int mi = 0; mi < 4; mi++)
#pragma unroll
        for (int nj = 0; nj < 4; nj++)
#pragma unroll
            for (int e = 0; e < 4; e++) acc[mi][nj][e] = 0.f;

    // staging: thread handles rows {t>>3 + j*32}, 16B chunk (t&7)
    const int rowT = t >> 3;
    const int chT  = t & 7;
    const __nv_bfloat16* Ag = A  + (size_t)(row0 + rowT) * 1024 + chT * 8;
    const __nv_bfloat16* Bg = Bw + (size_t)(col0 + rowT) * 1024 + chT * 8;
    const uint32_t sAst = sAu + (uint32_t)rowT * 144 + chT * 16;
    const uint32_t sBst = sBu + (uint32_t)rowT * 144 + chT * 16;

    for (int c = 0; c < 24; c++) {
        const int s  = c >> 3;
        const int k0 = (c & 7) * 64;
        const int aCol = ((s == 1) ? 512 : 0) + k0;   // pass1: A-lo
        const int bCol = ((s == 2) ? 512 : 0) + k0;   // pass2: B-lo
        uint4 av[4], bv[4];
#pragma unroll
        for (int j = 0; j < 4; j++) {
            av[j] = *(const uint4*)(Ag + (size_t)j * 32 * 1024 + aCol);
            bv[j] = *(const uint4*)(Bg + (size_t)j * 32 * 1024 + bCol);
        }
        __syncthreads();   // previous chunk's ldmatrix done before overwrite
#pragma unroll
        for (int j = 0; j < 4; j++) {
            asm volatile("st.shared.v4.b32 [%0], {%1,%2,%3,%4};"
                :: "r"(sAst + j * 32 * 144), "r"(av[j].x), "r"(av[j].y), "r"(av[j].z), "r"(av[j].w)
                : "memory");
            asm volatile("st.shared.v4.b32 [%0], {%1,%2,%3,%4};"
                :: "r"(sBst + j * 32 * 144), "r"(bv[j].x), "r"(bv[j].y), "r"(bv[j].z), "r"(bv[j].w)
                : "memory");
        }
        __syncthreads();

#pragma unroll
        for (int ks = 0; ks < 4; ks++) {
            uint32_t ar[4][4], br[2][4];
#pragma unroll
            for (int mi = 0; mi < 4; mi++)
                ldsm_x4(ar[mi][0], ar[mi][1], ar[mi][2], ar[mi][3],
                        aLane + (uint32_t)mi * 16 * 144 + ks * 32);
#pragma unroll
            for (int pj = 0; pj < 2; pj++)
                ldsm_x4(br[pj][0], br[pj][1], br[pj][2], br[pj][3],
                        bLane + (uint32_t)pj * 16 * 144 + ks * 32);
#pragma unroll
            for (int mi = 0; mi < 4; mi++)
#pragma unroll
                for (int nj = 0; nj < 4; nj++) {
                    const int pj = nj >> 1, hb = (nj & 1) * 2;
                    mma_bf16(acc[mi][nj], ar[mi][0], ar[mi][1], ar[mi][2], ar[mi][3],
                             br[pj][hb], br[pj][hb + 1]);
                }
        }
    }

    // epilogue: c0,c1 -> (row, col..col+1); c2,c3 -> (row+8, ...)
    const int rbase = row0 + wm * 64 + (lane >> 2);
    const int cbase = col0 + wn * 32 + (lane & 3) * 2;
#pragma unroll
    for (int mi = 0; mi < 4; mi++) {
#pragma unroll
        for (int nj = 0; nj < 4; nj++) {
            const int r  = rbase + mi * 16;
            const int cc = cbase + nj * 8;
            float b0 = 0.f, b1 = 0.f;
            if (bias) { b0 = bias[cc]; b1 = bias[cc + 1]; }
            *(float2*)(C + (size_t)r * Nc + cc) =
                make_float2(acc[mi][nj][0] + b0, acc[mi][nj][1] + b1);
            *(float2*)(C + (size_t)(r + 8) * Nc + cc) =
                make_float2(acc[mi][nj][2] + b0, acc[mi][nj][3] + b1);
        }
    }
}

// ---------------- attention (unchanged from round 3, ~480us) ------------------
#define AP   145
#define VP   68
#define QT_OFF 0
#define KT_OFF (64 * AP)
#define V_OFF  (2 * 64 * AP)
#define PT_OFF (2 * 64 * AP + 144 * VP)
#define ATTN_SMEM_FLOATS (2 * 64 * AP + 144 * VP + 144 * AP)
#define ATTN_SMEM_BYTES  (ATTN_SMEM_FLOATS * 4)

__global__ __launch_bounds__(256, 1)
void attn_kernel(const float* __restrict__ q, const float* __restrict__ kv,
                 float* __restrict__ o)
{
    extern __shared__ float sm[];
    float* Qt = sm + QT_OFF;
    float* Kt = sm + KT_OFF;
    float* Vs = sm + V_OFF;
    float* Pt = sm + PT_OFF;
    float* red = Pt;

    const int b = blockIdx.x >> 3;
    const int h = blockIdx.x & 7;
    const int t = threadIdx.x;
    const int ty = t >> 4;
    const int tx = t & 15;

    const float* qb = q  + (size_t)b * 144 * 512  + h * 64;
    const float* kb = kv + (size_t)b * 144 * 1024 + h * 64;
    const float* vb = kb + 512;

    for (int i = t; i < 144 * 64; i += 256) {
        int r = i >> 6, k = i & 63;
        Qt[k * AP + r] = qb[(size_t)r * 512 + k] * SCALE_;
        Kt[k * AP + r] = kb[(size_t)r * 1024 + k];
    }
    for (int i = t; i < 144 * 16; i += 256) {
        int n = i >> 4, cc = (i & 15) << 2;
        *(float4*)(Vs + n * VP + cc) = *(const float4*)(vb + (size_t)n * 1024 + cc);
    }
    __syncthreads();

    float acc[9][9];
#pragma unroll
    for (int i = 0; i < 9; i++)
#pragma unroll
        for (int j = 0; j < 9; j++) acc[i][j] = 0.f;

    const float* Qb = Qt + ty * 9;
    const float* Kb = Kt + tx * 9;
#pragma unroll 2
    for (int k = 0; k < 64; k++) {
        float qv[9], kvv[9];
#pragma unroll
        for (int i = 0; i < 9; i++) qv[i]  = Qb[k * AP + i];
#pragma unroll
        for (int j = 0; j < 9; j++) kvv[j] = Kb[k * AP + j];
#pragma unroll
        for (int i = 0; i < 9; i++)
#pragma unroll
            for (int j = 0; j < 9; j++) acc[i][j] += qv[i] * kvv[j];
    }

#pragma unroll
    for (int i = 0; i < 9; i++) {
        float m = acc[i][0];
#pragma unroll
        for (int j = 1; j < 9; j++) m = fmaxf(m, acc[i][j]);
        red[(ty * 9 + i) * 17 + tx] = m;
    }
    __syncthreads();
    float mrow[9];
#pragma unroll
    for (int i = 0; i < 9; i++) {
        const float* rr = red + (ty * 9 + i) * 17;
        float m = rr[0];
#pragma unroll
        for (int u = 1; u < 16; u++) m = fmaxf(m, rr[u]);
        mrow[i] = m;
    }
    __syncthreads();
#pragma unroll
    for (int i = 0; i < 9; i++) {
        float s = 0.f;
#pragma unroll
        for (int j = 0; j < 9; j++) {
            float e = __expf(acc[i][j] - mrow[i]);
            acc[i][j] = e;
            s += e;
        }
        red[(ty * 9 + i) * 17 + tx] = s;
    }
    __syncthreads();
    float inv[9];
#pragma unroll
    for (int i = 0; i < 9; i++) {
        const float* rr = red + (ty * 9 + i) * 17;
        float s = rr[0];
#pragma unroll
        for (int u = 1; u < 16; u++) s += rr[u];
        inv[i] = 1.f / s;
    }
    __syncthreads();

#pragma unroll
    for (int j = 0; j < 9; j++)
#pragma unroll
        for (int i = 0; i < 9; i++)
            Pt[(tx * 9 + j) * AP + (ty * 9 + i)] = acc[i][j];
    __syncthreads();

    float out[9][4];
#pragma unroll
    for (int i = 0; i < 9; i++)
#pragma unroll
        for (int d = 0; d < 4; d++) out[i][d] = 0.f;

    const float* Pb = Pt + ty * 9;
#pragma unroll 2
    for (int j = 0; j < 144; j++) {
        float pv[9];
#pragma unroll
        for (int i = 0; i < 9; i++) pv[i] = Pb[j * AP + i];
        float4 vv = *(const float4*)(Vs + j * VP + tx * 4);
#pragma unroll
        for (int i = 0; i < 9; i++) {
            out[i][0] += pv[i] * vv.x;
            out[i][1] += pv[i] * vv.y;
            out[i][2] += pv[i] * vv.z;
            out[i][3] += pv[i] * vv.w;
        }
    }

    float* ob = o + (size_t)b * 144 * 512 + h * 64;
#pragma unroll
    for (int i = 0; i < 9; i++) {
        int r = ty * 9 + i;
        *(float4*)(ob + (size_t)r * 512 + tx * 4) =
            make_float4(out[i][0] * inv[i], out[i][1] * inv[i],
                        out[i][2] * inv[i], out[i][3] * inv[i]);
    }
}

// ---------------- launch -------------------------------------------------------
extern "C" void kernel_launch(void* const* d_in, const int* in_sizes, int n_in,
                              void* d_out, int out_size)
{
    const float* x      = (const float*)d_in[0];
    const float* topo   = (const float*)d_in[1];
    const float* kv_w   = (const float*)d_in[2];
    const float* q_w    = (const float*)d_in[3];
    const float* proj_w = (const float*)d_in[4];
    const float* proj_b = (const float*)d_in[5];
    const int*   is_end = (const int*)d_in[6];

    void *pkv, *pq, *patt, *pxte, *pxe, *pae, *pwkv, *pwq, *pwp;
    cudaGetSymbolAddress(&pkv,  g_kv);
    cudaGetSymbolAddress(&pq,   g_q);
    cudaGetSymbolAddress(&patt, g_att);
    cudaGetSymbolAddress(&pxte, g_xte);
    cudaGetSymbolAddress(&pxe,  g_xe);
    cudaGetSymbolAddress(&pae,  g_ae);
    cudaGetSymbolAddress(&pwkv, g_wkve);
    cudaGetSymbolAddress(&pwq,  g_wqe);
    cudaGetSymbolAddress(&pwp,  g_wpe);

    cudaFuncSetAttribute(attn_kernel, cudaFuncAttributeMaxDynamicSharedMemorySize,
                         ATTN_SMEM_BYTES);

    const long act4 = (long)M_ * 512 / 4;
    const long wkv4 = 1024L * 512 / 4;
    const long w4   = 512L * 512 / 4;
    const int  TB   = 256;

    // conversions (fp32 -> bf16 hi|lo)
    split_dual_kernel<<<(unsigned)((act4 + TB - 1) / TB), TB>>>(
        (const float4*)x, (const float4*)topo, is_end,
        (__nv_bfloat16*)pxe, (__nv_bfloat16*)pxte, act4);
    split_bf16_kernel<<<(unsigned)((wkv4 + TB - 1) / TB), TB>>>(
        (const float4*)kv_w, (__nv_bfloat16*)pwkv, wkv4);
    split_bf16_kernel<<<(unsigned)((w4 + TB - 1) / TB), TB>>>(
        (const float4*)q_w, (__nv_bfloat16*)pwq, w4);
    split_bf16_kernel<<<(unsigned)((w4 + TB - 1) / TB), TB>>>(
        (const float4*)proj_w, (__nv_bfloat16*)pwp, w4);

    // KV = (x + is_end*topo) @ kv_w^T   [36864 x 1024]
    gemm_mma_kernel<<<dim3(8, 288), 256>>>(
        (const __nv_bfloat16*)pxte, (const __nv_bfloat16*)pwkv, nullptr, (float*)pkv, 1024);
    // Q = x @ q_w^T                      [36864 x 512]
    gemm_mma_kernel<<<dim3(4, 288), 256>>>(
        (const __nv_bfloat16*)pxe, (const __nv_bfloat16*)pwq, nullptr, (float*)pq, 512);
    // attention -> g_att [b,n,h,e]
    attn_kernel<<<B_ * 8, 256, ATTN_SMEM_BYTES>>>((float*)pq, (float*)pkv, (float*)patt);
    // convert attention output, then out = att @ proj_w^T + proj_b
    split_bf16_kernel<<<(unsigned)((act4 + TB - 1) / TB), TB>>>(
        (const float4*)patt, (__nv_bfloat16*)pae, act4);
    gemm_mma_kernel<<<dim3(4, 288), 256>>>(
        (const __nv_bfloat16*)pae, (const __nv_bfloat16*)pwp, proj_b, (float*)d_out, 512);
}